// round 12
// baseline (speedup 1.0000x reference)
#include <cuda_runtime.h>
#include <cuda_bf16.h>
#include <stdint.h>

#define NA 50000
#define EE 524288
#define FA 133
#define FB 14
#define HH 128
#define KWI 80   // init K=147 padded 160, bf16x2 words
#define KWU 128  // update K=256
#define KWR 64   // readout K=128
#define NTILES (EE / 128)   // 4096
#define UPD_GRID 148

// h stored as bf16x2 words [E][64]
__device__ uint32_t g_h0[(size_t)EE * 64];
__device__ uint32_t g_h1[(size_t)EE * 64];
__device__ __align__(16) float g_sum[(size_t)NA * HH];
__device__ __align__(16) float g_S2[(size_t)NA * HH];   // sum @ W2^T
__device__ int g_deg[NA];
__device__ int g_rowstart[NA + 1];
__device__ int g_cursor[NA];
__device__ int g_elist[EE];
// weights k-pair-major: word(kw, n) = bf16x2(w[n][2kw], w[n][2kw+1])
__device__ uint32_t g_WiH[KWI * HH];
__device__ uint32_t g_WiL[KWI * HH];
__device__ uint32_t g_WuH[KWU * HH];
__device__ uint32_t g_WuL[KWU * HH];
__device__ uint32_t g_WrH[KWR * HH];
__device__ uint32_t g_WrL[KWR * HH];

// ---------------- helpers ----------------
__device__ __forceinline__ uint32_t pack_bf2(float lo, float hi) {
    uint32_t r;
    asm("{ .reg .b16 a, b;\n\t"
        "cvt.rn.bf16.f32 a, %1;\n\t"
        "cvt.rn.bf16.f32 b, %2;\n\t"
        "mov.b32 %0, {a, b}; }"
        : "=r"(r) : "f"(lo), "f"(hi));
    return r;
}
__device__ __forceinline__ float2 unpack_bf2(uint32_t w) {
    __nv_bfloat162 v = *reinterpret_cast<__nv_bfloat162*>(&w);
    return make_float2(__bfloat162float(v.x), __bfloat162float(v.y));
}
__device__ __forceinline__ uint32_t smem_u32(const void* p) {
    uint32_t a;
    asm("{ .reg .u64 t; cvta.to.shared.u64 t, %1; cvt.u32.u64 %0, t; }" : "=r"(a) : "l"(p));
    return a;
}
__device__ __forceinline__ void cp_async16(uint32_t dst, const void* src) {
    asm volatile("cp.async.cg.shared.global [%0], [%1], 16;" :: "r"(dst), "l"(src) : "memory");
}
__device__ __forceinline__ void cp_commit() {
    asm volatile("cp.async.commit_group;" ::: "memory");
}
__device__ __forceinline__ void cp_wait0() {
    asm volatile("cp.async.wait_group 0;" ::: "memory");
}
__device__ __forceinline__ void mma16(float* c, const unsigned* a, const unsigned* b) {
    asm volatile(
        "mma.sync.aligned.m16n8k16.row.col.f32.bf16.bf16.f32 "
        "{%0,%1,%2,%3}, {%4,%5,%6,%7}, {%8,%9}, {%0,%1,%2,%3};"
        : "+f"(c[0]), "+f"(c[1]), "+f"(c[2]), "+f"(c[3])
        : "r"(a[0]), "r"(a[1]), "r"(a[2]), "r"(a[3]), "r"(b[0]), "r"(b[1]));
}

// ---------------- mma.sync helpers for init/readout/s2 (proven) -------------
__device__ __forceinline__ void mma_chunk(float C[2][8][4], const uint32_t* Xs, int xst,
                                          int kwBase, const uint32_t* Wh, const uint32_t* Wl,
                                          int wm0, int wn0, int g, int t) {
#pragma unroll
    for (int s = 0; s < 2; s++) {
        int kA = kwBase + s * 8 + t;
        unsigned a[2][4];
#pragma unroll
        for (int mi = 0; mi < 2; mi++) {
            int m0 = wm0 + mi * 16 + g;
            int swz = (m0 & 7) << 2;
            const uint32_t* x0 = Xs + (size_t)m0 * xst;
            const uint32_t* x8 = x0 + 8 * xst;
            a[mi][0] = x0[kA ^ swz];
            a[mi][1] = x8[kA ^ swz];
            a[mi][2] = x0[(kA + 4) ^ swz];
            a[mi][3] = x8[(kA + 4) ^ swz];
        }
        int r0 = (s * 8 + t) * 136, r1 = (s * 8 + t + 4) * 136;
#pragma unroll
        for (int ni = 0; ni < 8; ni++) {
            int cn = wn0 + ni * 8 + g;
            unsigned bh[2] = {Wh[r0 + cn], Wh[r1 + cn]};
            unsigned bl[2] = {Wl[r0 + cn], Wl[r1 + cn]};
            mma16(C[0][ni], a[0], bh);
            mma16(C[1][ni], a[1], bh);
            mma16(C[0][ni], a[0], bl);
            mma16(C[1][ni], a[1], bl);
        }
    }
}
__device__ __forceinline__ void ldg_w(uint4 rh[2], uint4 rl[2], const uint32_t* WH,
                                      const uint32_t* WL, int c, int tid) {
#pragma unroll
    for (int i = 0; i < 2; i++) {
        int u = tid * 2 + i;
        int kw = u >> 5, n4 = u & 31;
        rh[i] = *(const uint4*)(WH + (c * 16 + kw) * 128 + n4 * 4);
        rl[i] = *(const uint4*)(WL + (c * 16 + kw) * 128 + n4 * 4);
    }
}
__device__ __forceinline__ void sts_w(const uint4 rh[2], const uint4 rl[2], uint32_t* Wh,
                                      uint32_t* Wl, int tid) {
#pragma unroll
    for (int i = 0; i < 2; i++) {
        int u = tid * 2 + i;
        int kw = u >> 5, n4 = u & 31;
        *(uint4*)(Wh + kw * 136 + n4 * 4) = rh[i];
        *(uint4*)(Wl + kw * 136 + n4 * 4) = rl[i];
    }
}

// ---------------- weight prep ----------------
__global__ void prep_w_kernel(const float* __restrict__ W, int K, int kwTot, int which) {
    uint32_t *Wh, *Wl;
    if (which == 0) { Wh = g_WiH; Wl = g_WiL; }
    else if (which == 1) { Wh = g_WuH; Wl = g_WuL; }
    else { Wh = g_WrH; Wl = g_WrL; }
    int idx = blockIdx.x * 256 + threadIdx.x;
    if (idx >= kwTot * HH) return;
    int kw = idx >> 7, n = idx & 127;
    int k0 = 2 * kw;
    float w0 = (k0 < K) ? W[n * K + k0] : 0.f;
    float w1 = (k0 + 1 < K) ? W[n * K + k0 + 1] : 0.f;
    float h0 = __bfloat162float(__float2bfloat16_rn(w0));
    float h1 = __bfloat162float(__float2bfloat16_rn(w1));
    Wh[idx] = pack_bf2(h0, h1);
    Wl[idx] = pack_bf2(w0 - h0, w1 - h1);
}

// ---------------- CSR build ----------------
__global__ void zero_deg_kernel() {
    int i = blockIdx.x * 256 + threadIdx.x;
    if (i < NA) g_deg[i] = 0;
}
__global__ void hist_kernel(const int* __restrict__ ei) {
    int e = blockIdx.x * 256 + threadIdx.x;
    if (e < EE) atomicAdd(&g_deg[ei[EE + e]], 1);
}
__global__ void scan_kernel() {
    __shared__ int part[1024];
    int t = threadIdx.x;
    const int per = (NA + 1023) / 1024;
    int base0 = t * per;
    int s = 0;
    for (int i = 0; i < per; i++) {
        int n = base0 + i;
        if (n < NA) s += g_deg[n];
    }
    part[t] = s;
    __syncthreads();
    for (int off = 1; off < 1024; off <<= 1) {
        int v = 0;
        if (t >= off) v = part[t - off];
        __syncthreads();
        if (t >= off) part[t] += v;
        __syncthreads();
    }
    int run = (t == 0) ? 0 : part[t - 1];
    for (int i = 0; i < per; i++) {
        int n = base0 + i;
        if (n < NA) {
            g_rowstart[n] = run;
            g_cursor[n] = run;
            run += g_deg[n];
        }
    }
    if (t == 0) g_rowstart[NA] = part[1023];
}
__global__ void fill_kernel(const int* __restrict__ ei) {
    int e = blockIdx.x * 256 + threadIdx.x;
    if (e < EE) {
        int d = ei[EE + e];
        int p = atomicAdd(&g_cursor[d], 1);
        g_elist[p] = e;
    }
}

// ---------------- segment sum ----------------
__global__ void segsum_kernel(int hsel) {
    const uint32_t* hin = hsel ? g_h1 : g_h0;
    int gid = blockIdx.x * blockDim.x + threadIdx.x;
    int w = gid >> 5, lane = gid & 31;
    if (w >= NA) return;
    int s = g_rowstart[w], epos = g_rowstart[w + 1];
    float4 acc = {0.f, 0.f, 0.f, 0.f};
    for (int i = s; i < epos; i++) {
        int e = g_elist[i];
        uint2 v = *reinterpret_cast<const uint2*>(hin + (size_t)e * 64 + lane * 2);
        float2 p0 = unpack_bf2(v.x), p1 = unpack_bf2(v.y);
        acc.x += p0.x; acc.y += p0.y; acc.z += p1.x; acc.w += p1.y;
    }
    *reinterpret_cast<float4*>(g_sum + (size_t)w * HH + lane * 4) = acc;
}

// ---------------- S2 = sum @ W2^T (N-side GEMM, K=128, hi+lo) ----------------
__global__ void __launch_bounds__(256) s2_gemm() {
    extern __shared__ char sm[];
    uint32_t* Xs = (uint32_t*)sm;            // [128][64] words, swizzled
    uint32_t* Wh = Xs + 128 * 64;
    uint32_t* Wl = Wh + 16 * 136;
    int tid = threadIdx.x;
    int a0 = blockIdx.x * 128;
    for (int lin = tid; lin < 128 * 64; lin += 256) {
        int m = lin >> 6, kw = lin & 63;
        int an = a0 + m;
        float2 v = make_float2(0.f, 0.f);
        if (an < NA) v = *reinterpret_cast<const float2*>(g_sum + (size_t)an * HH + 2 * kw);
        Xs[m * 64 + (kw ^ ((m & 7) << 2))] = pack_bf2(v.x, v.y);
    }
    float C[2][8][4];
#pragma unroll
    for (int i = 0; i < 2; i++)
#pragma unroll
        for (int j = 0; j < 8; j++)
#pragma unroll
            for (int q = 0; q < 4; q++) C[i][j][q] = 0.f;
    int warp = tid >> 5, lane = tid & 31, g = lane >> 2, t = lane & 3;
    int wm0 = (warp >> 1) * 32, wn0 = (warp & 1) * 64;

    uint4 rh[2], rl[2];
    ldg_w(rh, rl, g_WuH, g_WuL, 4, tid);   // W2 = rows 64..127 (chunks 4..7)
    for (int c = 0; c < 4; c++) {
        __syncthreads();
        sts_w(rh, rl, Wh, Wl, tid);
        __syncthreads();
        if (c < 3) ldg_w(rh, rl, g_WuH, g_WuL, c + 5, tid);
        mma_chunk(C, Xs, 64, c * 16, Wh, Wl, wm0, wn0, g, t);
    }
#pragma unroll
    for (int mi = 0; mi < 2; mi++)
#pragma unroll
        for (int ni = 0; ni < 8; ni++) {
            int r0 = wm0 + mi * 16 + g, r1 = r0 + 8;
            int cidx = wn0 + ni * 8 + 2 * t;
            if (a0 + r0 < NA) {
                *(float2*)(g_S2 + (size_t)(a0 + r0) * HH + cidx) =
                    make_float2(C[mi][ni][0], C[mi][ni][1]);
            }
            if (a0 + r1 < NA) {
                *(float2*)(g_S2 + (size_t)(a0 + r1) * HH + cidx) =
                    make_float2(C[mi][ni][2], C[mi][ni][3]);
            }
        }
}

// ---------------- init GEMM (proven) ----------------
__global__ void __launch_bounds__(256) init_gemm(const float* __restrict__ atom,
                                                 const float* __restrict__ bond,
                                                 const int* __restrict__ ei,
                                                 const float* __restrict__ binit) {
    extern __shared__ char sm[];
    uint32_t* Xs = (uint32_t*)sm;
    uint32_t* Wh = Xs + 128 * 96;
    uint32_t* Wl = Wh + 16 * 136;
    int* ssrc = (int*)(Wl + 16 * 136);
    float* sbias = (float*)(ssrc + 128);
    int tid = threadIdx.x;
    int e0 = blockIdx.x * 128;
    if (tid < 128) {
        ssrc[tid] = ei[e0 + tid];
        sbias[tid] = binit[tid];
    }
    __syncthreads();
    for (int lin = tid; lin < 128 * KWI; lin += 256) {
        int m = lin / KWI, kw = lin - m * KWI;
        int k0 = 2 * kw;
        int src = ssrc[m];
        float v0, v1;
        if (k0 < FA) v0 = atom[(size_t)src * FA + k0];
        else if (k0 < FA + FB) v0 = bond[(size_t)(e0 + m) * FB + (k0 - FA)];
        else v0 = 0.f;
        int k1 = k0 + 1;
        if (k1 < FA) v1 = atom[(size_t)src * FA + k1];
        else if (k1 < FA + FB) v1 = bond[(size_t)(e0 + m) * FB + (k1 - FA)];
        else v1 = 0.f;
        Xs[m * 96 + (kw ^ ((m & 7) << 2))] = pack_bf2(v0, v1);
    }
    float C[2][8][4];
#pragma unroll
    for (int i = 0; i < 2; i++)
#pragma unroll
        for (int j = 0; j < 8; j++)
#pragma unroll
            for (int q = 0; q < 4; q++) C[i][j][q] = 0.f;
    int warp = tid >> 5, lane = tid & 31, g = lane >> 2, t = lane & 3;
    int wm0 = (warp >> 1) * 32, wn0 = (warp & 1) * 64;

    uint4 rh[2], rl[2];
    ldg_w(rh, rl, g_WiH, g_WiL, 0, tid);
    for (int c = 0; c < 5; c++) {
        __syncthreads();
        sts_w(rh, rl, Wh, Wl, tid);
        __syncthreads();
        if (c < 4) ldg_w(rh, rl, g_WiH, g_WiL, c + 1, tid);
        mma_chunk(C, Xs, 96, c * 16, Wh, Wl, wm0, wn0, g, t);
    }
#pragma unroll
    for (int mi = 0; mi < 2; mi++)
#pragma unroll
        for (int ni = 0; ni < 8; ni++) {
            int r0 = wm0 + mi * 16 + g, r1 = r0 + 8;
            int cidx = wn0 + ni * 8 + 2 * t;
            int wc = (wn0 >> 1) + ni * 4 + t;
            float b0 = sbias[cidx], b1 = sbias[cidx + 1];
            g_h0[(size_t)(e0 + r0) * 64 + wc] =
                pack_bf2(fmaxf(C[mi][ni][0] + b0, 0.f), fmaxf(C[mi][ni][1] + b1, 0.f));
            g_h0[(size_t)(e0 + r1) * 64 + wc] =
                pack_bf2(fmaxf(C[mi][ni][2] + b0, 0.f), fmaxf(C[mi][ni][3] + b1, 0.f));
        }
}

// ---------------- persistent update GEMM: dual-accumulator, pure-LDS frags --
// h' = relu(h@W1^T + S2[src] - (h@W2^T)[rev] + b)
// SMEM (words): WH [128][136] | WL [128][136] | XH 2x[128][64] | ssrc 2x128 | sbias 128
#define XSTR 64
#define UPD_SMEM_WORDS (128 * 136 * 2 + 2 * 128 * 64 + 256 + 128)

__device__ __forceinline__ void load_frags_h(uint32_t fr[16], const uint32_t* Xc,
                                             int kwBase, int wm0, int g, int t) {
#pragma unroll
    for (int s = 0; s < 2; s++)
#pragma unroll
        for (int mi = 0; mi < 2; mi++) {
            int row = wm0 + mi * 16 + g;
            int swz = (row & 7) << 2;
            int kA = kwBase + s * 8 + t;
            const uint32_t* x0 = Xc + (size_t)row * XSTR;
            const uint32_t* x8 = x0 + 8 * XSTR;
            fr[s * 8 + mi * 4 + 0] = x0[kA ^ swz];
            fr[s * 8 + mi * 4 + 1] = x8[kA ^ swz];
            fr[s * 8 + mi * 4 + 2] = x0[(kA + 4) ^ swz];
            fr[s * 8 + mi * 4 + 3] = x8[(kA + 4) ^ swz];
        }
}
__device__ __forceinline__ void consume2(float C1[2][8][4], float C2[2][8][4],
                                         const uint32_t fr[16], const uint32_t* WH,
                                         const uint32_t* WL, int c, int wn0, int g, int t) {
#pragma unroll
    for (int s = 0; s < 2; s++) {
        const unsigned* a0 = fr + s * 8;
        const unsigned* a1 = fr + s * 8 + 4;
        int r0 = (c * 16 + s * 8 + t) * 136, r1 = r0 + 4 * 136;
        int q0 = r0 + 64 * 136, q1 = r1 + 64 * 136;   // W2 rows
#pragma unroll
        for (int ni = 0; ni < 8; ni++) {
            int cn = wn0 + ni * 8 + g;
            unsigned b1h[2] = {WH[r0 + cn], WH[r1 + cn]};
            unsigned b1l[2] = {WL[r0 + cn], WL[r1 + cn]};
            unsigned b2h[2] = {WH[q0 + cn], WH[q1 + cn]};
            unsigned b2l[2] = {WL[q0 + cn], WL[q1 + cn]};
            mma16(C1[0][ni], a0, b1h);
            mma16(C1[1][ni], a1, b1h);
            mma16(C1[0][ni], a0, b1l);
            mma16(C1[1][ni], a1, b1l);
            mma16(C2[0][ni], a0, b2h);
            mma16(C2[1][ni], a1, b2h);
            mma16(C2[0][ni], a0, b2l);
            mma16(C2[1][ni], a1, b2l);
        }
    }
}

__global__ void __launch_bounds__(256, 1) update_p(const int* __restrict__ ei,
                                                   const float* __restrict__ bupd, int hsel) {
    extern __shared__ __align__(16) uint32_t smw[];
    uint32_t* WH = smw;                      // [128][136]
    uint32_t* WL = WH + 128 * 136;           // [128][136]
    uint32_t* XH = WL + 128 * 136;           // 2 x [128][64]
    int* ssrc = (int*)(XH + 2 * 128 * XSTR); // 2 x 128
    float* sbias = (float*)(ssrc + 256);     // 128
    const uint32_t* hin = hsel ? g_h1 : g_h0;
    uint32_t* hout = hsel ? g_h0 : g_h1;
    int tid = threadIdx.x;
    uint32_t xh_sm = smem_u32(XH);

    // resident weights (W1 rows 0..63, W2 rows 64..127)
    for (int u = tid; u < 4096; u += 256) {
        int kw = u >> 5, n4 = u & 31;
        *(uint4*)(WH + kw * 136 + n4 * 4) = ((const uint4*)g_WuH)[u];
        *(uint4*)(WL + kw * 136 + n4 * 4) = ((const uint4*)g_WuL)[u];
    }
    if (tid < 128) sbias[tid] = bupd[tid];

    int warp = tid >> 5, lane = tid & 31, g = lane >> 2, t = lane & 3;
    int wm0 = (warp >> 1) * 32, wn0 = (warp & 1) * 64;

    int tile = blockIdx.x;
    if (tile < NTILES) {
        int e0 = tile * 128;
        for (int it = tid; it < 2048; it += 256) {
            int m = it >> 4, j = it & 15;
            cp_async16(xh_sm + (m * XSTR + ((j * 4) ^ ((m & 7) << 2))) * 4,
                       hin + (size_t)(e0 + m) * 64 + j * 4);
        }
        cp_commit();
        if (tid < 128) ssrc[tid] = ei[e0 + tid];
    }

    int buf = 0;
    for (; tile < NTILES; tile += gridDim.x) {
        int e0 = tile * 128;
        int nxt = tile + gridDim.x;
        cp_wait0();
        __syncthreads();
        if (nxt < NTILES) {
            int ne0 = nxt * 128;
            int ob = buf ^ 1;
            uint32_t dst0 = xh_sm + ob * (128 * XSTR * 4);
            for (int it = tid; it < 2048; it += 256) {
                int m = it >> 4, j = it & 15;
                cp_async16(dst0 + (m * XSTR + ((j * 4) ^ ((m & 7) << 2))) * 4,
                           hin + (size_t)(ne0 + m) * 64 + j * 4);
            }
            cp_commit();
            if (tid < 128) ssrc[ob * 128 + tid] = ei[ne0 + tid];
        }
        const uint32_t* Xc = XH + buf * (128 * XSTR);
        const int* sc = ssrc + buf * 128;

        float C1[2][8][4], C2[2][8][4];
#pragma unroll
        for (int i = 0; i < 2; i++)
#pragma unroll
            for (int j = 0; j < 8; j++)
#pragma unroll
                for (int q = 0; q < 4; q++) { C1[i][j][q] = 0.f; C2[i][j][q] = 0.f; }

        uint32_t fr[16];
#pragma unroll
        for (int c = 0; c < 4; c++) {
            load_frags_h(fr, Xc, c * 16, wm0, g, t);
            consume2(C1, C2, fr, WH, WL, c, wn0, g, t);
        }
        // epilogue: h' = relu(C1 + S2[src] - shfl_xor(C2, 4) + b)
#pragma unroll
        for (int mi = 0; mi < 2; mi++)
#pragma unroll
            for (int ni = 0; ni < 8; ni++) {
                int r0 = wm0 + mi * 16 + g, r1 = r0 + 8;
                int cidx = wn0 + ni * 8 + 2 * t;
                int wc = (wn0 >> 1) + ni * 4 + t;
                float y2a0 = __shfl_xor_sync(0xFFFFFFFFu, C2[mi][ni][0], 4);
                float y2a1 = __shfl_xor_sync(0xFFFFFFFFu, C2[mi][ni][1], 4);
                float y2b0 = __shfl_xor_sync(0xFFFFFFFFu, C2[mi][ni][2], 4);
                float y2b1 = __shfl_xor_sync(0xFFFFFFFFu, C2[mi][ni][3], 4);
                float2 s2a = *(const float2*)(g_S2 + (size_t)sc[r0] * HH + cidx);
                float2 s2b = *(const float2*)(g_S2 + (size_t)sc[r1] * HH + cidx);
                float b0 = sbias[cidx], b1 = sbias[cidx + 1];
                hout[(size_t)(e0 + r0) * 64 + wc] =
                    pack_bf2(fmaxf(C1[mi][ni][0] + s2a.x - y2a0 + b0, 0.f),
                             fmaxf(C1[mi][ni][1] + s2a.y - y2a1 + b1, 0.f));
                hout[(size_t)(e0 + r1) * 64 + wc] =
                    pack_bf2(fmaxf(C1[mi][ni][2] + s2b.x - y2b0 + b0, 0.f),
                             fmaxf(C1[mi][ni][3] + s2b.y - y2b1 + b1, 0.f));
            }
        buf ^= 1;
    }
}

// ---------------- readout (proven) ----------------
__global__ void __launch_bounds__(256) readout_kernel(const float* __restrict__ bread,
                                                      float* __restrict__ out) {
    extern __shared__ char sm[];
    uint32_t* Xs = (uint32_t*)sm;
    uint32_t* Wh = Xs + 128 * 64;
    uint32_t* Wl = Wh + 16 * 136;
    float* sbias = (float*)(Wl + 16 * 136);
    float* sred = sbias + 128;
    int tid = threadIdx.x;
    int a0 = blockIdx.x * 128;
    if (tid < 128) {
        sbias[tid] = bread[tid];
        sred[tid] = 0.f;
    }
    for (int lin = tid; lin < 128 * KWR; lin += 256) {
        int m = lin >> 6, kw = lin & 63;
        int an = a0 + m;
        float2 v = make_float2(0.f, 0.f);
        if (an < NA) v = *reinterpret_cast<const float2*>(g_sum + (size_t)an * HH + 2 * kw);
        Xs[m * 64 + (kw ^ ((m & 7) << 2))] = pack_bf2(v.x, v.y);
    }
    float C[2][8][4];
#pragma unroll
    for (int i = 0; i < 2; i++)
#pragma unroll
        for (int j = 0; j < 8; j++)
#pragma unroll
            for (int q = 0; q < 4; q++) C[i][j][q] = 0.f;
    int warp = tid >> 5, lane = tid & 31, g = lane >> 2, t = lane & 3;
    int wm0 = (warp >> 1) * 32, wn0 = (warp & 1) * 64;

    uint4 rh[2], rl[2];
    ldg_w(rh, rl, g_WrH, g_WrL, 0, tid);
    for (int c = 0; c < 4; c++) {
        __syncthreads();
        sts_w(rh, rl, Wh, Wl, tid);
        __syncthreads();
        if (c < 3) ldg_w(rh, rl, g_WrH, g_WrL, c + 1, tid);
        mma_chunk(C, Xs, 64, c * 16, Wh, Wl, wm0, wn0, g, t);
    }
#pragma unroll
    for (int mi = 0; mi < 2; mi++)
#pragma unroll
        for (int ni = 0; ni < 8; ni++) {
            int r0 = wm0 + mi * 16 + g, r1 = r0 + 8;
            int cidx = wn0 + ni * 8 + 2 * t;
            bool v0 = (a0 + r0) < NA, v1 = (a0 + r1) < NA;
            float b0 = sbias[cidx], b1 = sbias[cidx + 1];
            float s0 = (v0 ? fmaxf(C[mi][ni][0] + b0, 0.f) : 0.f) +
                       (v1 ? fmaxf(C[mi][ni][2] + b0, 0.f) : 0.f);
            float s1 = (v0 ? fmaxf(C[mi][ni][1] + b1, 0.f) : 0.f) +
                       (v1 ? fmaxf(C[mi][ni][3] + b1, 0.f) : 0.f);
            atomicAdd(&sred[cidx], s0);
            atomicAdd(&sred[cidx + 1], s1);
        }
    __syncthreads();
    if (tid < 128) atomicAdd(&out[tid], sred[tid]);
}

__global__ void zero_out_kernel(float* out) {
    if (threadIdx.x < HH) out[threadIdx.x] = 0.f;
}

extern "C" void kernel_launch(void* const* d_in, const int* in_sizes, int n_in,
                              void* d_out, int out_size) {
    const float* atom = (const float*)d_in[0];
    const float* bond = (const float*)d_in[1];
    const int* ei = (const int*)d_in[2];
    const float* Wi = (const float*)d_in[3];
    const float* bi = (const float*)d_in[4];
    const float* Wu = (const float*)d_in[5];
    const float* bu = (const float*)d_in[6];
    const float* Wr = (const float*)d_in[7];
    const float* br = (const float*)d_in[8];
    float* out = (float*)d_out;

    const int INIT_SMEM = (128 * 96 + 2 * 16 * 136) * 4 + 256 * 4;
    const int READ_SMEM = (128 * 64 + 2 * 16 * 136) * 4 + 256 * 4;
    const int S2_SMEM = (128 * 64 + 2 * 16 * 136) * 4;
    const int UPD_SMEM = UPD_SMEM_WORDS * 4;
    cudaFuncSetAttribute(init_gemm, cudaFuncAttributeMaxDynamicSharedMemorySize, INIT_SMEM);
    cudaFuncSetAttribute(update_p, cudaFuncAttributeMaxDynamicSharedMemorySize, UPD_SMEM);
    cudaFuncSetAttribute(readout_kernel, cudaFuncAttributeMaxDynamicSharedMemorySize, READ_SMEM);
    cudaFuncSetAttribute(s2_gemm, cudaFuncAttributeMaxDynamicSharedMemorySize, S2_SMEM);

    zero_deg_kernel<<<(NA + 255) / 256, 256>>>();
    hist_kernel<<<EE / 256, 256>>>(ei);
    scan_kernel<<<1, 1024>>>();
    fill_kernel<<<EE / 256, 256>>>(ei);

    prep_w_kernel<<<(KWI * HH) / 256, 256>>>(Wi, FA + FB, KWI, 0);
    prep_w_kernel<<<(KWU * HH) / 256, 256>>>(Wu, 2 * HH, KWU, 1);
    prep_w_kernel<<<(KWR * HH) / 256, 256>>>(Wr, HH, KWR, 2);

    init_gemm<<<EE / 128, 256, INIT_SMEM>>>(atom, bond, ei, bi);

    int cur = 0;
    for (int d = 0; d < 3; d++) {
        segsum_kernel<<<(NA * 32 + 255) / 256, 256>>>(cur);
        s2_gemm<<<(NA + 127) / 128, 256, S2_SMEM>>>();
        update_p<<<UPD_GRID, 256, UPD_SMEM>>>(ei, bu, cur);
        cur ^= 1;
    }
    segsum_kernel<<<(NA * 32 + 255) / 256, 256>>>(cur);

    zero_out_kernel<<<1, 128>>>(out);
    readout_kernel<<<(NA + 127) / 128, 256, READ_SMEM>>>(br, out);
}

// round 13
// speedup vs baseline: 1.3583x; 1.3583x over previous
#include <cuda_runtime.h>
#include <cuda_fp16.h>
#include <stdint.h>

#define NA 50000
#define EE 524288
#define FA 133
#define FB 14
#define HH 128
#define KWI 80   // init K=147 padded 160, fp16x2 words
#define KWU 128  // update K=256
#define KWR 64   // readout K=128
#define NTILES (EE / 128)   // 4096
#define UPD_GRID 148

// h stored as fp16x2 words [E][64]
__device__ uint32_t g_h0[(size_t)EE * 64];
__device__ uint32_t g_h1[(size_t)EE * 64];
__device__ __align__(16) float g_sum[(size_t)NA * HH];
__device__ int g_deg[NA];
__device__ int g_rowstart[NA + 1];
__device__ int g_cursor[NA];
__device__ int g_elist[EE];
// weights k-pair-major fp16: word(kw, n) = fp16x2(w[n][2kw], w[n][2kw+1])
__device__ uint32_t g_WiH[KWI * HH];
__device__ uint32_t g_WuH[KWU * HH];
__device__ uint32_t g_WrH[KWR * HH];

// ---------------- helpers ----------------
__device__ __forceinline__ uint32_t pack_hf2(float lo, float hi) {
    uint32_t r;
    asm("{ .reg .b16 a, b;\n\t"
        "cvt.rn.f16.f32 a, %1;\n\t"
        "cvt.rn.f16.f32 b, %2;\n\t"
        "mov.b32 %0, {a, b}; }"
        : "=r"(r) : "f"(lo), "f"(hi));
    return r;
}
__device__ __forceinline__ float2 unpack_hf2(uint32_t w) {
    __half2 v = *reinterpret_cast<__half2*>(&w);
    return __half22float2(v);
}
__device__ __forceinline__ uint32_t smem_u32(const void* p) {
    uint32_t a;
    asm("{ .reg .u64 t; cvta.to.shared.u64 t, %1; cvt.u32.u64 %0, t; }" : "=r"(a) : "l"(p));
    return a;
}
__device__ __forceinline__ void cp_async16(uint32_t dst, const void* src) {
    asm volatile("cp.async.cg.shared.global [%0], [%1], 16;" :: "r"(dst), "l"(src) : "memory");
}
__device__ __forceinline__ void cp_commit() {
    asm volatile("cp.async.commit_group;" ::: "memory");
}
__device__ __forceinline__ void cp_wait0() {
    asm volatile("cp.async.wait_group 0;" ::: "memory");
}
__device__ __forceinline__ void mma16(float* c, const unsigned* a, const unsigned* b) {
    asm volatile(
        "mma.sync.aligned.m16n8k16.row.col.f32.f16.f16.f32 "
        "{%0,%1,%2,%3}, {%4,%5,%6,%7}, {%8,%9}, {%0,%1,%2,%3};"
        : "+f"(c[0]), "+f"(c[1]), "+f"(c[2]), "+f"(c[3])
        : "r"(a[0]), "r"(a[1]), "r"(a[2]), "r"(a[3]), "r"(b[0]), "r"(b[1]));
}

// ---------------- mma helpers for init/readout ----------------
__device__ __forceinline__ void mma_chunk(float C[2][8][4], const uint32_t* Xs, int xst,
                                          int kwBase, const uint32_t* Wh,
                                          int wm0, int wn0, int g, int t) {
#pragma unroll
    for (int s = 0; s < 2; s++) {
        int kA = kwBase + s * 8 + t;
        unsigned a[2][4];
#pragma unroll
        for (int mi = 0; mi < 2; mi++) {
            int m0 = wm0 + mi * 16 + g;
            int swz = (m0 & 7) << 2;
            const uint32_t* x0 = Xs + (size_t)m0 * xst;
            const uint32_t* x8 = x0 + 8 * xst;
            a[mi][0] = x0[kA ^ swz];
            a[mi][1] = x8[kA ^ swz];
            a[mi][2] = x0[(kA + 4) ^ swz];
            a[mi][3] = x8[(kA + 4) ^ swz];
        }
        int r0 = (s * 8 + t) * 136, r1 = (s * 8 + t + 4) * 136;
#pragma unroll
        for (int ni = 0; ni < 8; ni++) {
            int cn = wn0 + ni * 8 + g;
            unsigned bh[2] = {Wh[r0 + cn], Wh[r1 + cn]};
            mma16(C[0][ni], a[0], bh);
            mma16(C[1][ni], a[1], bh);
        }
    }
}
__device__ __forceinline__ void ldg_w(uint4 rh[2], const uint32_t* WH, int c, int tid) {
#pragma unroll
    for (int i = 0; i < 2; i++) {
        int u = tid * 2 + i;
        int kw = u >> 5, n4 = u & 31;
        rh[i] = *(const uint4*)(WH + (c * 16 + kw) * 128 + n4 * 4);
    }
}
__device__ __forceinline__ void sts_w(const uint4 rh[2], uint32_t* Wh, int tid) {
#pragma unroll
    for (int i = 0; i < 2; i++) {
        int u = tid * 2 + i;
        int kw = u >> 5, n4 = u & 31;
        *(uint4*)(Wh + kw * 136 + n4 * 4) = rh[i];
    }
}

// ---------------- weight prep (fp16 single) ----------------
__global__ void prep_w_kernel(const float* __restrict__ W, int K, int kwTot, int which) {
    uint32_t* Wh;
    if (which == 0) Wh = g_WiH;
    else if (which == 1) Wh = g_WuH;
    else Wh = g_WrH;
    int idx = blockIdx.x * 256 + threadIdx.x;
    if (idx >= kwTot * HH) return;
    int kw = idx >> 7, n = idx & 127;
    int k0 = 2 * kw;
    float w0 = (k0 < K) ? W[n * K + k0] : 0.f;
    float w1 = (k0 + 1 < K) ? W[n * K + k0 + 1] : 0.f;
    Wh[idx] = pack_hf2(w0, w1);
}

// ---------------- CSR build ----------------
__global__ void zero_deg_kernel() {
    int i = blockIdx.x * 256 + threadIdx.x;
    if (i < NA) g_deg[i] = 0;
}
__global__ void hist_kernel(const int* __restrict__ ei) {
    int e = blockIdx.x * 256 + threadIdx.x;
    if (e < EE) atomicAdd(&g_deg[ei[EE + e]], 1);
}
__global__ void scan_kernel() {
    __shared__ int part[1024];
    int t = threadIdx.x;
    const int per = (NA + 1023) / 1024;
    int base0 = t * per;
    int s = 0;
    for (int i = 0; i < per; i++) {
        int n = base0 + i;
        if (n < NA) s += g_deg[n];
    }
    part[t] = s;
    __syncthreads();
    for (int off = 1; off < 1024; off <<= 1) {
        int v = 0;
        if (t >= off) v = part[t - off];
        __syncthreads();
        if (t >= off) part[t] += v;
        __syncthreads();
    }
    int run = (t == 0) ? 0 : part[t - 1];
    for (int i = 0; i < per; i++) {
        int n = base0 + i;
        if (n < NA) {
            g_rowstart[n] = run;
            g_cursor[n] = run;
            run += g_deg[n];
        }
    }
    if (t == 0) g_rowstart[NA] = part[1023];
}
__global__ void fill_kernel(const int* __restrict__ ei) {
    int e = blockIdx.x * 256 + threadIdx.x;
    if (e < EE) {
        int d = ei[EE + e];
        int p = atomicAdd(&g_cursor[d], 1);
        g_elist[p] = e;
    }
}

// ---------------- segment sum ----------------
__global__ void segsum_kernel(int hsel) {
    const uint32_t* hin = hsel ? g_h1 : g_h0;
    int gid = blockIdx.x * blockDim.x + threadIdx.x;
    int w = gid >> 5, lane = gid & 31;
    if (w >= NA) return;
    int s = g_rowstart[w], epos = g_rowstart[w + 1];
    float4 acc = {0.f, 0.f, 0.f, 0.f};
    for (int i = s; i < epos; i++) {
        int e = g_elist[i];
        uint2 v = *reinterpret_cast<const uint2*>(hin + (size_t)e * 64 + lane * 2);
        float2 p0 = unpack_hf2(v.x), p1 = unpack_hf2(v.y);
        acc.x += p0.x; acc.y += p0.y; acc.z += p1.x; acc.w += p1.y;
    }
    *reinterpret_cast<float4*>(g_sum + (size_t)w * HH + lane * 4) = acc;
}

// ---------------- init GEMM ----------------
__global__ void __launch_bounds__(256) init_gemm(const float* __restrict__ atom,
                                                 const float* __restrict__ bond,
                                                 const int* __restrict__ ei,
                                                 const float* __restrict__ binit) {
    extern __shared__ char sm[];
    uint32_t* Xs = (uint32_t*)sm;            // [128][96] words (kw 0..79)
    uint32_t* Wh = Xs + 128 * 96;            // [16][136]
    int* ssrc = (int*)(Wh + 16 * 136);
    float* sbias = (float*)(ssrc + 128);
    int tid = threadIdx.x;
    int e0 = blockIdx.x * 128;
    if (tid < 128) {
        ssrc[tid] = ei[e0 + tid];
        sbias[tid] = binit[tid];
    }
    __syncthreads();
    for (int lin = tid; lin < 128 * KWI; lin += 256) {
        int m = lin / KWI, kw = lin - m * KWI;
        int k0 = 2 * kw;
        int src = ssrc[m];
        float v0, v1;
        if (k0 < FA) v0 = atom[(size_t)src * FA + k0];
        else if (k0 < FA + FB) v0 = bond[(size_t)(e0 + m) * FB + (k0 - FA)];
        else v0 = 0.f;
        int k1 = k0 + 1;
        if (k1 < FA) v1 = atom[(size_t)src * FA + k1];
        else if (k1 < FA + FB) v1 = bond[(size_t)(e0 + m) * FB + (k1 - FA)];
        else v1 = 0.f;
        Xs[m * 96 + (kw ^ ((m & 7) << 2))] = pack_hf2(v0, v1);
    }
    float C[2][8][4];
#pragma unroll
    for (int i = 0; i < 2; i++)
#pragma unroll
        for (int j = 0; j < 8; j++)
#pragma unroll
            for (int q = 0; q < 4; q++) C[i][j][q] = 0.f;
    int warp = tid >> 5, lane = tid & 31, g = lane >> 2, t = lane & 3;
    int wm0 = (warp >> 1) * 32, wn0 = (warp & 1) * 64;

    uint4 rh[2];
    ldg_w(rh, g_WiH, 0, tid);
    for (int c = 0; c < 5; c++) {
        __syncthreads();
        sts_w(rh, Wh, tid);
        __syncthreads();
        if (c < 4) ldg_w(rh, g_WiH, c + 1, tid);
        mma_chunk(C, Xs, 96, c * 16, Wh, wm0, wn0, g, t);
    }
#pragma unroll
    for (int mi = 0; mi < 2; mi++)
#pragma unroll
        for (int ni = 0; ni < 8; ni++) {
            int r0 = wm0 + mi * 16 + g, r1 = r0 + 8;
            int cidx = wn0 + ni * 8 + 2 * t;
            int wc = (wn0 >> 1) + ni * 4 + t;
            float b0 = sbias[cidx], b1 = sbias[cidx + 1];
            g_h0[(size_t)(e0 + r0) * 64 + wc] =
                pack_hf2(fmaxf(C[mi][ni][0] + b0, 0.f), fmaxf(C[mi][ni][1] + b1, 0.f));
            g_h0[(size_t)(e0 + r1) * 64 + wc] =
                pack_hf2(fmaxf(C[mi][ni][2] + b0, 0.f), fmaxf(C[mi][ni][3] + b1, 0.f));
        }
}

// ---------------- persistent pipelined update GEMM (R9 structure, fp16) -----
// SMEM (words): WH [128][136] | XH 2x[128][64] | ssrc 2x128 | sbias 128
#define XSTR 64
#define UPD_SMEM_WORDS (128 * 136 + 2 * 128 * 64 + 256 + 128)

__device__ __forceinline__ uint32_t frag_word(const uint32_t* Xc, const int* sc,
                                              int row, int kw) {
    if (kw < 64) {
        return Xc[row * XSTR + (kw ^ ((row & 7) << 2))];
    } else {
        int kwm = kw - 64;
        int rrev = row ^ 1;
        float2 s = *(const float2*)(g_sum + (size_t)sc[row] * HH + 2 * kwm);
        float2 hr = unpack_hf2(Xc[rrev * XSTR + (kwm ^ ((rrev & 7) << 2))]);
        return pack_hf2(s.x - hr.x, s.y - hr.y);
    }
}
__device__ __forceinline__ void load_frags(uint32_t fr[16], const uint32_t* Xc, const int* sc,
                                           int kwBase, int wm0, int g, int t) {
#pragma unroll
    for (int s = 0; s < 2; s++)
#pragma unroll
        for (int mi = 0; mi < 2; mi++) {
            int row = wm0 + mi * 16 + g;
            int kA = kwBase + s * 8 + t;
            fr[s * 8 + mi * 4 + 0] = frag_word(Xc, sc, row, kA);
            fr[s * 8 + mi * 4 + 1] = frag_word(Xc, sc, row + 8, kA);
            fr[s * 8 + mi * 4 + 2] = frag_word(Xc, sc, row, kA + 4);
            fr[s * 8 + mi * 4 + 3] = frag_word(Xc, sc, row + 8, kA + 4);
        }
}
__device__ __forceinline__ void consume(float C[2][8][4], const uint32_t fr[16],
                                        const uint32_t* WH, int kwBase,
                                        int wn0, int g, int t) {
#pragma unroll
    for (int s = 0; s < 2; s++) {
        const unsigned* a0 = fr + s * 8;
        const unsigned* a1 = fr + s * 8 + 4;
        int r0 = (kwBase + s * 8 + t) * 136, r1 = r0 + 4 * 136;
#pragma unroll
        for (int ni = 0; ni < 8; ni++) {
            int cn = wn0 + ni * 8 + g;
            unsigned bh[2] = {WH[r0 + cn], WH[r1 + cn]};
            mma16(C[0][ni], a0, bh);
            mma16(C[1][ni], a1, bh);
        }
    }
}

__global__ void __launch_bounds__(256, 1) update_p(const int* __restrict__ ei,
                                                   const float* __restrict__ bupd, int hsel) {
    extern __shared__ __align__(16) uint32_t smw[];
    uint32_t* WH = smw;                      // [128][136]
    uint32_t* XH = WH + 128 * 136;           // 2 x [128][64]
    int* ssrc = (int*)(XH + 2 * 128 * XSTR); // 2 x 128
    float* sbias = (float*)(ssrc + 256);     // 128
    const uint32_t* hin = hsel ? g_h1 : g_h0;
    uint32_t* hout = hsel ? g_h0 : g_h1;
    int tid = threadIdx.x;
    uint32_t xh_sm = smem_u32(XH);

    // resident weights
    for (int u = tid; u < 4096; u += 256) {
        int kw = u >> 5, n4 = u & 31;
        *(uint4*)(WH + kw * 136 + n4 * 4) = ((const uint4*)g_WuH)[u];
    }
    if (tid < 128) sbias[tid] = bupd[tid];

    int warp = tid >> 5, lane = tid & 31, g = lane >> 2, t = lane & 3;
    int wm0 = (warp >> 1) * 32, wn0 = (warp & 1) * 64;

    int tile = blockIdx.x;
    if (tile < NTILES) {
        int e0 = tile * 128;
        for (int it = tid; it < 2048; it += 256) {
            int m = it >> 4, j = it & 15;
            cp_async16(xh_sm + (m * XSTR + ((j * 4) ^ ((m & 7) << 2))) * 4,
                       hin + (size_t)(e0 + m) * 64 + j * 4);
        }
        cp_commit();
        if (tid < 128) ssrc[tid] = ei[e0 + tid];
    }

    int buf = 0;
    for (; tile < NTILES; tile += gridDim.x) {
        int e0 = tile * 128;
        int nxt = tile + gridDim.x;
        cp_wait0();
        __syncthreads();
        if (nxt < NTILES) {
            int ne0 = nxt * 128;
            int ob = buf ^ 1;
            uint32_t dst0 = xh_sm + ob * (128 * XSTR * 4);
            for (int it = tid; it < 2048; it += 256) {
                int m = it >> 4, j = it & 15;
                cp_async16(dst0 + (m * XSTR + ((j * 4) ^ ((m & 7) << 2))) * 4,
                           hin + (size_t)(ne0 + m) * 64 + j * 4);
            }
            cp_commit();
            if (tid < 128) ssrc[ob * 128 + tid] = ei[ne0 + tid];
        }
        const uint32_t* Xc = XH + buf * (128 * XSTR);
        const int* sc = ssrc + buf * 128;

        float C[2][8][4];
#pragma unroll
        for (int i = 0; i < 2; i++)
#pragma unroll
            for (int j = 0; j < 8; j++)
#pragma unroll
                for (int q = 0; q < 4; q++) C[i][j][q] = 0.f;

        uint32_t fr[2][16];
        load_frags(fr[0], Xc, sc, 0, wm0, g, t);
#pragma unroll
        for (int c = 0; c < 8; c++) {
            if (c < 7) load_frags(fr[(c + 1) & 1], Xc, sc, (c + 1) * 16, wm0, g, t);
            consume(C, fr[c & 1], WH, c * 16, wn0, g, t);
        }
        // epilogue
#pragma unroll
        for (int mi = 0; mi < 2; mi++)
#pragma unroll
            for (int ni = 0; ni < 8; ni++) {
                int r0 = wm0 + mi * 16 + g, r1 = r0 + 8;
                int cidx = wn0 + ni * 8 + 2 * t;
                int wc = (wn0 >> 1) + ni * 4 + t;
                float b0 = sbias[cidx], b1 = sbias[cidx + 1];
                hout[(size_t)(e0 + r0) * 64 + wc] =
                    pack_hf2(fmaxf(C[mi][ni][0] + b0, 0.f), fmaxf(C[mi][ni][1] + b1, 0.f));
                hout[(size_t)(e0 + r1) * 64 + wc] =
                    pack_hf2(fmaxf(C[mi][ni][2] + b0, 0.f), fmaxf(C[mi][ni][3] + b1, 0.f));
            }
        buf ^= 1;
    }
}

// ---------------- readout ----------------
__global__ void __launch_bounds__(256) readout_kernel(const float* __restrict__ bread,
                                                      float* __restrict__ out) {
    extern __shared__ char sm[];
    uint32_t* Xs = (uint32_t*)sm;            // [128][64]
    uint32_t* Wh = Xs + 128 * 64;
    float* sbias = (float*)(Wh + 16 * 136);
    float* sred = sbias + 128;
    int tid = threadIdx.x;
    int a0 = blockIdx.x * 128;
    if (tid < 128) {
        sbias[tid] = bread[tid];
        sred[tid] = 0.f;
    }
    for (int lin = tid; lin < 128 * KWR; lin += 256) {
        int m = lin >> 6, kw = lin & 63;
        int an = a0 + m;
        float2 v = make_float2(0.f, 0.f);
        if (an < NA) v = *reinterpret_cast<const float2*>(g_sum + (size_t)an * HH + 2 * kw);
        Xs[m * 64 + (kw ^ ((m & 7) << 2))] = pack_hf2(v.x, v.y);
    }
    float C[2][8][4];
#pragma unroll
    for (int i = 0; i < 2; i++)
#pragma unroll
        for (int j = 0; j < 8; j++)
#pragma unroll
            for (int q = 0; q < 4; q++) C[i][j][q] = 0.f;
    int warp = tid >> 5, lane = tid & 31, g = lane >> 2, t = lane & 3;
    int wm0 = (warp >> 1) * 32, wn0 = (warp & 1) * 64;

    uint4 rh[2];
    ldg_w(rh, g_WrH, 0, tid);
    for (int c = 0; c < 4; c++) {
        __syncthreads();
        sts_w(rh, Wh, tid);
        __syncthreads();
        if (c < 3) ldg_w(rh, g_WrH, c + 1, tid);
        mma_chunk(C, Xs, 64, c * 16, Wh, wm0, wn0, g, t);
    }
#pragma unroll
    for (int mi = 0; mi < 2; mi++)
#pragma unroll
        for (int ni = 0; ni < 8; ni++) {
            int r0 = wm0 + mi * 16 + g, r1 = r0 + 8;
            int cidx = wn0 + ni * 8 + 2 * t;
            bool v0 = (a0 + r0) < NA, v1 = (a0 + r1) < NA;
            float b0 = sbias[cidx], b1 = sbias[cidx + 1];
            float s0 = (v0 ? fmaxf(C[mi][ni][0] + b0, 0.f) : 0.f) +
                       (v1 ? fmaxf(C[mi][ni][2] + b0, 0.f) : 0.f);
            float s1 = (v0 ? fmaxf(C[mi][ni][1] + b1, 0.f) : 0.f) +
                       (v1 ? fmaxf(C[mi][ni][3] + b1, 0.f) : 0.f);
            atomicAdd(&sred[cidx], s0);
            atomicAdd(&sred[cidx + 1], s1);
        }
    __syncthreads();
    if (tid < 128) atomicAdd(&out[tid], sred[tid]);
}

__global__ void zero_out_kernel(float* out) {
    if (threadIdx.x < HH) out[threadIdx.x] = 0.f;
}

extern "C" void kernel_launch(void* const* d_in, const int* in_sizes, int n_in,
                              void* d_out, int out_size) {
    const float* atom = (const float*)d_in[0];
    const float* bond = (const float*)d_in[1];
    const int* ei = (const int*)d_in[2];
    const float* Wi = (const float*)d_in[3];
    const float* bi = (const float*)d_in[4];
    const float* Wu = (const float*)d_in[5];
    const float* bu = (const float*)d_in[6];
    const float* Wr = (const float*)d_in[7];
    const float* br = (const float*)d_in[8];
    float* out = (float*)d_out;

    const int INIT_SMEM = (128 * 96 + 16 * 136) * 4 + 256 * 4;
    const int READ_SMEM = (128 * 64 + 16 * 136) * 4 + 256 * 4;
    const int UPD_SMEM = UPD_SMEM_WORDS * 4;
    cudaFuncSetAttribute(init_gemm, cudaFuncAttributeMaxDynamicSharedMemorySize, INIT_SMEM);
    cudaFuncSetAttribute(update_p, cudaFuncAttributeMaxDynamicSharedMemorySize, UPD_SMEM);
    cudaFuncSetAttribute(readout_kernel, cudaFuncAttributeMaxDynamicSharedMemorySize, READ_SMEM);

    zero_deg_kernel<<<(NA + 255) / 256, 256>>>();
    hist_kernel<<<EE / 256, 256>>>(ei);
    scan_kernel<<<1, 1024>>>();
    fill_kernel<<<EE / 256, 256>>>(ei);

    prep_w_kernel<<<(KWI * HH) / 256, 256>>>(Wi, FA + FB, KWI, 0);
    prep_w_kernel<<<(KWU * HH) / 256, 256>>>(Wu, 2 * HH, KWU, 1);
    prep_w_kernel<<<(KWR * HH) / 256, 256>>>(Wr, HH, KWR, 2);

    init_gemm<<<EE / 128, 256, INIT_SMEM>>>(atom, bond, ei, bi);

    int cur = 0;
    for (int d = 0; d < 3; d++) {
        segsum_kernel<<<(NA * 32 + 255) / 256, 256>>>(cur);
        update_p<<<UPD_GRID, 256, UPD_SMEM>>>(ei, bu, cur);
        cur ^= 1;
    }
    segsum_kernel<<<(NA * 32 + 255) / 256, 256>>>(cur);

    zero_out_kernel<<<1, 128>>>(out);
    readout_kernel<<<(NA + 127) / 128, 256, READ_SMEM>>>(br, out);
}

// round 14
// speedup vs baseline: 1.4262x; 1.0500x over previous
#include <cuda_runtime.h>
#include <cuda_fp16.h>
#include <stdint.h>

#define NA 50000
#define EE 524288
#define FA 133
#define FB 14
#define HH 128
#define KWI 80   // init K=147 padded 160, fp16x2 words
#define KWU 128  // update K=256
#define KWR 64   // readout K=128
#define NTILES (EE / 128)   // 4096
#define UPD_GRID 148

// h stored as fp16x2 words [E][64]
__device__ uint32_t g_h0[(size_t)EE * 64];
__device__ uint32_t g_h1[(size_t)EE * 64];
// segment sums, fp16x2 words [N][64]
__device__ uint32_t g_sumh[(size_t)NA * 64];
__device__ int g_deg[NA];
__device__ int g_rowstart[NA + 1];
__device__ int g_cursor[NA];
__device__ int g_elist[EE];
// weights k-pair-major fp16: word(kw, n) = fp16x2(w[n][2kw], w[n][2kw+1])
__device__ uint32_t g_WiH[KWI * HH];
__device__ uint32_t g_WuH[KWU * HH];
__device__ uint32_t g_WrH[KWR * HH];

// ---------------- helpers ----------------
__device__ __forceinline__ uint32_t pack_hf2(float lo, float hi) {
    uint32_t r;
    asm("{ .reg .b16 a, b;\n\t"
        "cvt.rn.f16.f32 a, %1;\n\t"
        "cvt.rn.f16.f32 b, %2;\n\t"
        "mov.b32 %0, {a, b}; }"
        : "=r"(r) : "f"(lo), "f"(hi));
    return r;
}
__device__ __forceinline__ float2 unpack_hf2(uint32_t w) {
    __half2 v = *reinterpret_cast<__half2*>(&w);
    return __half22float2(v);
}
__device__ __forceinline__ uint32_t smem_u32(const void* p) {
    uint32_t a;
    asm("{ .reg .u64 t; cvta.to.shared.u64 t, %1; cvt.u32.u64 %0, t; }" : "=r"(a) : "l"(p));
    return a;
}
__device__ __forceinline__ void cp_async16(uint32_t dst, const void* src) {
    asm volatile("cp.async.cg.shared.global [%0], [%1], 16;" :: "r"(dst), "l"(src) : "memory");
}
__device__ __forceinline__ void cp_commit() {
    asm volatile("cp.async.commit_group;" ::: "memory");
}
__device__ __forceinline__ void cp_wait0() {
    asm volatile("cp.async.wait_group 0;" ::: "memory");
}
__device__ __forceinline__ void mma16(float* c, const unsigned* a, const unsigned* b) {
    asm volatile(
        "mma.sync.aligned.m16n8k16.row.col.f32.f16.f16.f32 "
        "{%0,%1,%2,%3}, {%4,%5,%6,%7}, {%8,%9}, {%0,%1,%2,%3};"
        : "+f"(c[0]), "+f"(c[1]), "+f"(c[2]), "+f"(c[3])
        : "r"(a[0]), "r"(a[1]), "r"(a[2]), "r"(a[3]), "r"(b[0]), "r"(b[1]));
}

// ---------------- mma helpers for init/readout ----------------
__device__ __forceinline__ void mma_chunk(float C[2][8][4], const uint32_t* Xs, int xst,
                                          int kwBase, const uint32_t* Wh,
                                          int wm0, int wn0, int g, int t) {
#pragma unroll
    for (int s = 0; s < 2; s++) {
        int kA = kwBase + s * 8 + t;
        unsigned a[2][4];
#pragma unroll
        for (int mi = 0; mi < 2; mi++) {
            int m0 = wm0 + mi * 16 + g;
            int swz = (m0 & 7) << 2;
            const uint32_t* x0 = Xs + (size_t)m0 * xst;
            const uint32_t* x8 = x0 + 8 * xst;
            a[mi][0] = x0[kA ^ swz];
            a[mi][1] = x8[kA ^ swz];
            a[mi][2] = x0[(kA + 4) ^ swz];
            a[mi][3] = x8[(kA + 4) ^ swz];
        }
        int r0 = (s * 8 + t) * 136, r1 = (s * 8 + t + 4) * 136;
#pragma unroll
        for (int ni = 0; ni < 8; ni++) {
            int cn = wn0 + ni * 8 + g;
            unsigned bh[2] = {Wh[r0 + cn], Wh[r1 + cn]};
            mma16(C[0][ni], a[0], bh);
            mma16(C[1][ni], a[1], bh);
        }
    }
}
__device__ __forceinline__ void ldg_w(uint4 rh[2], const uint32_t* WH, int c, int tid) {
#pragma unroll
    for (int i = 0; i < 2; i++) {
        int u = tid * 2 + i;
        int kw = u >> 5, n4 = u & 31;
        rh[i] = *(const uint4*)(WH + (c * 16 + kw) * 128 + n4 * 4);
    }
}
__device__ __forceinline__ void sts_w(const uint4 rh[2], uint32_t* Wh, int tid) {
#pragma unroll
    for (int i = 0; i < 2; i++) {
        int u = tid * 2 + i;
        int kw = u >> 5, n4 = u & 31;
        *(uint4*)(Wh + kw * 136 + n4 * 4) = rh[i];
    }
}

// ---------------- weight prep (fp16 single) ----------------
__global__ void prep_w_kernel(const float* __restrict__ W, int K, int kwTot, int which) {
    uint32_t* Wh;
    if (which == 0) Wh = g_WiH;
    else if (which == 1) Wh = g_WuH;
    else Wh = g_WrH;
    int idx = blockIdx.x * 256 + threadIdx.x;
    if (idx >= kwTot * HH) return;
    int kw = idx >> 7, n = idx & 127;
    int k0 = 2 * kw;
    float w0 = (k0 < K) ? W[n * K + k0] : 0.f;
    float w1 = (k0 + 1 < K) ? W[n * K + k0 + 1] : 0.f;
    Wh[idx] = pack_hf2(w0, w1);
}

// ---------------- CSR build ----------------
__global__ void zero_deg_kernel() {
    int i = blockIdx.x * 256 + threadIdx.x;
    if (i < NA) g_deg[i] = 0;
}
__global__ void hist_kernel(const int* __restrict__ ei) {
    int e = blockIdx.x * 256 + threadIdx.x;
    if (e < EE) atomicAdd(&g_deg[ei[EE + e]], 1);
}
__global__ void scan_kernel() {
    __shared__ int part[1024];
    int t = threadIdx.x;
    const int per = (NA + 1023) / 1024;
    int base0 = t * per;
    int s = 0;
    for (int i = 0; i < per; i++) {
        int n = base0 + i;
        if (n < NA) s += g_deg[n];
    }
    part[t] = s;
    __syncthreads();
    for (int off = 1; off < 1024; off <<= 1) {
        int v = 0;
        if (t >= off) v = part[t - off];
        __syncthreads();
        if (t >= off) part[t] += v;
        __syncthreads();
    }
    int run = (t == 0) ? 0 : part[t - 1];
    for (int i = 0; i < per; i++) {
        int n = base0 + i;
        if (n < NA) {
            g_rowstart[n] = run;
            g_cursor[n] = run;
            run += g_deg[n];
        }
    }
    if (t == 0) g_rowstart[NA] = part[1023];
}
__global__ void fill_kernel(const int* __restrict__ ei) {
    int e = blockIdx.x * 256 + threadIdx.x;
    if (e < EE) {
        int d = ei[EE + e];
        int p = atomicAdd(&g_cursor[d], 1);
        g_elist[p] = e;
    }
}

// ---------------- segment sum (MLP-4 unrolled, fp16 output) ----------------
__global__ void segsum_kernel(int hsel) {
    const uint32_t* hin = hsel ? g_h1 : g_h0;
    int gid = blockIdx.x * blockDim.x + threadIdx.x;
    int w = gid >> 5, lane = gid & 31;
    if (w >= NA) return;
    int s = g_rowstart[w], epos = g_rowstart[w + 1];
    float4 acc = {0.f, 0.f, 0.f, 0.f};
    int i = s;
    for (; i + 4 <= epos; i += 4) {
        int e0 = g_elist[i], e1 = g_elist[i + 1], e2 = g_elist[i + 2], e3 = g_elist[i + 3];
        uint2 v0 = *reinterpret_cast<const uint2*>(hin + (size_t)e0 * 64 + lane * 2);
        uint2 v1 = *reinterpret_cast<const uint2*>(hin + (size_t)e1 * 64 + lane * 2);
        uint2 v2 = *reinterpret_cast<const uint2*>(hin + (size_t)e2 * 64 + lane * 2);
        uint2 v3 = *reinterpret_cast<const uint2*>(hin + (size_t)e3 * 64 + lane * 2);
        float2 a0 = unpack_hf2(v0.x), b0 = unpack_hf2(v0.y);
        float2 a1 = unpack_hf2(v1.x), b1 = unpack_hf2(v1.y);
        float2 a2 = unpack_hf2(v2.x), b2 = unpack_hf2(v2.y);
        float2 a3 = unpack_hf2(v3.x), b3 = unpack_hf2(v3.y);
        acc.x += (a0.x + a1.x) + (a2.x + a3.x);
        acc.y += (a0.y + a1.y) + (a2.y + a3.y);
        acc.z += (b0.x + b1.x) + (b2.x + b3.x);
        acc.w += (b0.y + b1.y) + (b2.y + b3.y);
    }
    for (; i < epos; i++) {
        int e = g_elist[i];
        uint2 v = *reinterpret_cast<const uint2*>(hin + (size_t)e * 64 + lane * 2);
        float2 p0 = unpack_hf2(v.x), p1 = unpack_hf2(v.y);
        acc.x += p0.x; acc.y += p0.y; acc.z += p1.x; acc.w += p1.y;
    }
    uint2 outw;
    outw.x = pack_hf2(acc.x, acc.y);
    outw.y = pack_hf2(acc.z, acc.w);
    *reinterpret_cast<uint2*>(g_sumh + (size_t)w * 64 + lane * 2) = outw;
}

// ---------------- init GEMM ----------------
__global__ void __launch_bounds__(256) init_gemm(const float* __restrict__ atom,
                                                 const float* __restrict__ bond,
                                                 const int* __restrict__ ei,
                                                 const float* __restrict__ binit) {
    extern __shared__ char sm[];
    uint32_t* Xs = (uint32_t*)sm;            // [128][96] words (kw 0..79)
    uint32_t* Wh = Xs + 128 * 96;            // [16][136]
    int* ssrc = (int*)(Wh + 16 * 136);
    float* sbias = (float*)(ssrc + 128);
    int tid = threadIdx.x;
    int e0 = blockIdx.x * 128;
    if (tid < 128) {
        ssrc[tid] = ei[e0 + tid];
        sbias[tid] = binit[tid];
    }
    __syncthreads();
    for (int lin = tid; lin < 128 * KWI; lin += 256) {
        int m = lin / KWI, kw = lin - m * KWI;
        int k0 = 2 * kw;
        int src = ssrc[m];
        float v0, v1;
        if (k0 < FA) v0 = atom[(size_t)src * FA + k0];
        else if (k0 < FA + FB) v0 = bond[(size_t)(e0 + m) * FB + (k0 - FA)];
        else v0 = 0.f;
        int k1 = k0 + 1;
        if (k1 < FA) v1 = atom[(size_t)src * FA + k1];
        else if (k1 < FA + FB) v1 = bond[(size_t)(e0 + m) * FB + (k1 - FA)];
        else v1 = 0.f;
        Xs[m * 96 + (kw ^ ((m & 7) << 2))] = pack_hf2(v0, v1);
    }
    float C[2][8][4];
#pragma unroll
    for (int i = 0; i < 2; i++)
#pragma unroll
        for (int j = 0; j < 8; j++)
#pragma unroll
            for (int q = 0; q < 4; q++) C[i][j][q] = 0.f;
    int warp = tid >> 5, lane = tid & 31, g = lane >> 2, t = lane & 3;
    int wm0 = (warp >> 1) * 32, wn0 = (warp & 1) * 64;

    uint4 rh[2];
    ldg_w(rh, g_WiH, 0, tid);
    for (int c = 0; c < 5; c++) {
        __syncthreads();
        sts_w(rh, Wh, tid);
        __syncthreads();
        if (c < 4) ldg_w(rh, g_WiH, c + 1, tid);
        mma_chunk(C, Xs, 96, c * 16, Wh, wm0, wn0, g, t);
    }
#pragma unroll
    for (int mi = 0; mi < 2; mi++)
#pragma unroll
        for (int ni = 0; ni < 8; ni++) {
            int r0 = wm0 + mi * 16 + g, r1 = r0 + 8;
            int cidx = wn0 + ni * 8 + 2 * t;
            int wc = (wn0 >> 1) + ni * 4 + t;
            float b0 = sbias[cidx], b1 = sbias[cidx + 1];
            g_h0[(size_t)(e0 + r0) * 64 + wc] =
                pack_hf2(fmaxf(C[mi][ni][0] + b0, 0.f), fmaxf(C[mi][ni][1] + b1, 0.f));
            g_h0[(size_t)(e0 + r1) * 64 + wc] =
                pack_hf2(fmaxf(C[mi][ni][2] + b0, 0.f), fmaxf(C[mi][ni][3] + b1, 0.f));
        }
}

// ---------------- persistent pipelined update GEMM (fp16, HSUB2 m-frags) ----
// SMEM (words): WH [128][136] | XH 2x[128][64] | ssrc 2x128 | sbias 128
#define XSTR 64
#define UPD_SMEM_WORDS (128 * 136 + 2 * 128 * 64 + 256 + 128)

__device__ __forceinline__ uint32_t frag_word(const uint32_t* Xc, const int* sc,
                                              int row, int kw) {
    if (kw < 64) {
        return Xc[row * XSTR + (kw ^ ((row & 7) << 2))];
    } else {
        int kwm = kw - 64;
        int rrev = row ^ 1;
        uint32_t s = g_sumh[(size_t)sc[row] * 64 + kwm];
        uint32_t hr = Xc[rrev * XSTR + (kwm ^ ((rrev & 7) << 2))];
        __half2 d = __hsub2(*reinterpret_cast<__half2*>(&s), *reinterpret_cast<__half2*>(&hr));
        return *reinterpret_cast<uint32_t*>(&d);
    }
}
__device__ __forceinline__ void load_frags(uint32_t fr[16], const uint32_t* Xc, const int* sc,
                                           int kwBase, int wm0, int g, int t) {
#pragma unroll
    for (int s = 0; s < 2; s++)
#pragma unroll
        for (int mi = 0; mi < 2; mi++) {
            int row = wm0 + mi * 16 + g;
            int kA = kwBase + s * 8 + t;
            fr[s * 8 + mi * 4 + 0] = frag_word(Xc, sc, row, kA);
            fr[s * 8 + mi * 4 + 1] = frag_word(Xc, sc, row + 8, kA);
            fr[s * 8 + mi * 4 + 2] = frag_word(Xc, sc, row, kA + 4);
            fr[s * 8 + mi * 4 + 3] = frag_word(Xc, sc, row + 8, kA + 4);
        }
}
__device__ __forceinline__ void consume(float C[2][8][4], const uint32_t fr[16],
                                        const uint32_t* WH, int kwBase,
                                        int wn0, int g, int t) {
#pragma unroll
    for (int s = 0; s < 2; s++) {
        const unsigned* a0 = fr + s * 8;
        const unsigned* a1 = fr + s * 8 + 4;
        int r0 = (kwBase + s * 8 + t) * 136, r1 = r0 + 4 * 136;
#pragma unroll
        for (int ni = 0; ni < 8; ni++) {
            int cn = wn0 + ni * 8 + g;
            unsigned bh[2] = {WH[r0 + cn], WH[r1 + cn]};
            mma16(C[0][ni], a0, bh);
            mma16(C[1][ni], a1, bh);
        }
    }
}

__global__ void __launch_bounds__(256, 1) update_p(const int* __restrict__ ei,
                                                   const float* __restrict__ bupd, int hsel) {
    extern __shared__ __align__(16) uint32_t smw[];
    uint32_t* WH = smw;                      // [128][136]
    uint32_t* XH = WH + 128 * 136;           // 2 x [128][64]
    int* ssrc = (int*)(XH + 2 * 128 * XSTR); // 2 x 128
    float* sbias = (float*)(ssrc + 256);     // 128
    const uint32_t* hin = hsel ? g_h1 : g_h0;
    uint32_t* hout = hsel ? g_h0 : g_h1;
    int tid = threadIdx.x;
    uint32_t xh_sm = smem_u32(XH);

    // resident weights
    for (int u = tid; u < 4096; u += 256) {
        int kw = u >> 5, n4 = u & 31;
        *(uint4*)(WH + kw * 136 + n4 * 4) = ((const uint4*)g_WuH)[u];
    }
    if (tid < 128) sbias[tid] = bupd[tid];

    int warp = tid >> 5, lane = tid & 31, g = lane >> 2, t = lane & 3;
    int wm0 = (warp >> 1) * 32, wn0 = (warp & 1) * 64;

    int tile = blockIdx.x;
    if (tile < NTILES) {
        int e0 = tile * 128;
        for (int it = tid; it < 2048; it += 256) {
            int m = it >> 4, j = it & 15;
            cp_async16(xh_sm + (m * XSTR + ((j * 4) ^ ((m & 7) << 2))) * 4,
                       hin + (size_t)(e0 + m) * 64 + j * 4);
        }
        cp_commit();
        if (tid < 128) ssrc[tid] = ei[e0 + tid];
    }

    int buf = 0;
    for (; tile < NTILES; tile += gridDim.x) {
        int e0 = tile * 128;
        int nxt = tile + gridDim.x;
        cp_wait0();
        __syncthreads();
        if (nxt < NTILES) {
            int ne0 = nxt * 128;
            int ob = buf ^ 1;
            uint32_t dst0 = xh_sm + ob * (128 * XSTR * 4);
            for (int it = tid; it < 2048; it += 256) {
                int m = it >> 4, j = it & 15;
                cp_async16(dst0 + (m * XSTR + ((j * 4) ^ ((m & 7) << 2))) * 4,
                           hin + (size_t)(ne0 + m) * 64 + j * 4);
            }
            cp_commit();
            if (tid < 128) ssrc[ob * 128 + tid] = ei[ne0 + tid];
        }
        const uint32_t* Xc = XH + buf * (128 * XSTR);
        const int* sc = ssrc + buf * 128;

        float C[2][8][4];
#pragma unroll
        for (int i = 0; i < 2; i++)
#pragma unroll
            for (int j = 0; j < 8; j++)
#pragma unroll
                for (int q = 0; q < 4; q++) C[i][j][q] = 0.f;

        uint32_t fr[2][16];
        load_frags(fr[0], Xc, sc, 0, wm0, g, t);
#pragma unroll
        for (int c = 0; c < 8; c++) {
            if (c < 7) load_frags(fr[(c + 1) & 1], Xc, sc, (c + 1) * 16, wm0, g, t);
            consume(C, fr[c & 1], WH, c * 16, wn0, g, t);
        }
        // epilogue
#pragma unroll
        for (int mi = 0; mi < 2; mi++)
#pragma unroll
            for (int ni = 0; ni < 8; ni++) {
                int r0 = wm0 + mi * 16 + g, r1 = r0 + 8;
                int cidx = wn0 + ni * 8 + 2 * t;
                int wc = (wn0 >> 1) + ni * 4 + t;
                float b0 = sbias[cidx], b1 = sbias[cidx + 1];
                hout[(size_t)(e0 + r0) * 64 + wc] =
                    pack_hf2(fmaxf(C[mi][ni][0] + b0, 0.f), fmaxf(C[mi][ni][1] + b1, 0.f));
                hout[(size_t)(e0 + r1) * 64 + wc] =
                    pack_hf2(fmaxf(C[mi][ni][2] + b0, 0.f), fmaxf(C[mi][ni][3] + b1, 0.f));
            }
        buf ^= 1;
    }
}

// ---------------- readout ----------------
__global__ void __launch_bounds__(256) readout_kernel(const float* __restrict__ bread,
                                                      float* __restrict__ out) {
    extern __shared__ char sm[];
    uint32_t* Xs = (uint32_t*)sm;            // [128][64]
    uint32_t* Wh = Xs + 128 * 64;
    float* sbias = (float*)(Wh + 16 * 136);
    float* sred = sbias + 128;
    int tid = threadIdx.x;
    int a0 = blockIdx.x * 128;
    if (tid < 128) {
        sbias[tid] = bread[tid];
        sred[tid] = 0.f;
    }
    for (int lin = tid; lin < 128 * KWR; lin += 256) {
        int m = lin >> 6, kw = lin & 63;
        int an = a0 + m;
        uint32_t v = (an < NA) ? g_sumh[(size_t)an * 64 + kw] : 0u;
        Xs[m * 64 + (kw ^ ((m & 7) << 2))] = v;
    }
    float C[2][8][4];
#pragma unroll
    for (int i = 0; i < 2; i++)
#pragma unroll
        for (int j = 0; j < 8; j++)
#pragma unroll
            for (int q = 0; q < 4; q++) C[i][j][q] = 0.f;
    int warp = tid >> 5, lane = tid & 31, g = lane >> 2, t = lane & 3;
    int wm0 = (warp >> 1) * 32, wn0 = (warp & 1) * 64;

    uint4 rh[2];
    ldg_w(rh, g_WrH, 0, tid);
    for (int c = 0; c < 4; c++) {
        __syncthreads();
        sts_w(rh, Wh, tid);
        __syncthreads();
        if (c < 3) ldg_w(rh, g_WrH, c + 1, tid);
        mma_chunk(C, Xs, 64, c * 16, Wh, wm0, wn0, g, t);
    }
#pragma unroll
    for (int mi = 0; mi < 2; mi++)
#pragma unroll
        for (int ni = 0; ni < 8; ni++) {
            int r0 = wm0 + mi * 16 + g, r1 = r0 + 8;
            int cidx = wn0 + ni * 8 + 2 * t;
            bool v0 = (a0 + r0) < NA, v1 = (a0 + r1) < NA;
            float b0 = sbias[cidx], b1 = sbias[cidx + 1];
            float s0 = (v0 ? fmaxf(C[mi][ni][0] + b0, 0.f) : 0.f) +
                       (v1 ? fmaxf(C[mi][ni][2] + b0, 0.f) : 0.f);
            float s1 = (v0 ? fmaxf(C[mi][ni][1] + b1, 0.f) : 0.f) +
                       (v1 ? fmaxf(C[mi][ni][3] + b1, 0.f) : 0.f);
            atomicAdd(&sred[cidx], s0);
            atomicAdd(&sred[cidx + 1], s1);
        }
    __syncthreads();
    if (tid < 128) atomicAdd(&out[tid], sred[tid]);
}

__global__ void zero_out_kernel(float* out) {
    if (threadIdx.x < HH) out[threadIdx.x] = 0.f;
}

extern "C" void kernel_launch(void* const* d_in, const int* in_sizes, int n_in,
                              void* d_out, int out_size) {
    const float* atom = (const float*)d_in[0];
    const float* bond = (const float*)d_in[1];
    const int* ei = (const int*)d_in[2];
    const float* Wi = (const float*)d_in[3];
    const float* bi = (const float*)d_in[4];
    const float* Wu = (const float*)d_in[5];
    const float* bu = (const float*)d_in[6];
    const float* Wr = (const float*)d_in[7];
    const float* br = (const float*)d_in[8];
    float* out = (float*)d_out;

    const int INIT_SMEM = (128 * 96 + 16 * 136) * 4 + 256 * 4;
    const int READ_SMEM = (128 * 64 + 16 * 136) * 4 + 256 * 4;
    const int UPD_SMEM = UPD_SMEM_WORDS * 4;
    cudaFuncSetAttribute(init_gemm, cudaFuncAttributeMaxDynamicSharedMemorySize, INIT_SMEM);
    cudaFuncSetAttribute(update_p, cudaFuncAttributeMaxDynamicSharedMemorySize, UPD_SMEM);
    cudaFuncSetAttribute(readout_kernel, cudaFuncAttributeMaxDynamicSharedMemorySize, READ_SMEM);

    zero_deg_kernel<<<(NA + 255) / 256, 256>>>();
    hist_kernel<<<EE / 256, 256>>>(ei);
    scan_kernel<<<1, 1024>>>();
    fill_kernel<<<EE / 256, 256>>>(ei);

    prep_w_kernel<<<(KWI * HH) / 256, 256>>>(Wi, FA + FB, KWI, 0);
    prep_w_kernel<<<(KWU * HH) / 256, 256>>>(Wu, 2 * HH, KWU, 1);
    prep_w_kernel<<<(KWR * HH) / 256, 256>>>(Wr, HH, KWR, 2);

    init_gemm<<<EE / 128, 256, INIT_SMEM>>>(atom, bond, ei, bi);

    int cur = 0;
    for (int d = 0; d < 3; d++) {
        segsum_kernel<<<(NA * 32 + 255) / 256, 256>>>(cur);
        update_p<<<UPD_GRID, 256, UPD_SMEM>>>(ei, bu, cur);
        cur ^= 1;
    }
    segsum_kernel<<<(NA * 32 + 255) / 256, 256>>>(cur);

    zero_out_kernel<<<1, 128>>>(out);
    readout_kernel<<<(NA + 127) / 128, 256, READ_SMEM>>>(br, out);
}